// round 4
// baseline (speedup 1.0000x reference)
#include <cuda_runtime.h>
#include <cuda_bf16.h>
#include <cstdint>

#define B_ 256
#define L_ 512
#define H_ 768
#define K_ 64
#define M_ (B_*L_)

#define LOG2E 1.4426950408889634f
#define LN2   0.6931471805599453f
#define ESHIFT 6.0f

// -------- device scratch --------
__device__ float g_emit2[M_*K_];     // emit * log2(e)
__device__ float g_Tt2[K_*K_];       // Tt2[j][k] = T[k][j]*log2e (gold score)
__device__ float g_Et[K_*K_];        // Et[j][i]  = 2^(T[i][j]*log2e - 6)
__device__ float g_Wtf[K_*H_];       // W^T f32 [n][h]
__device__ int   g_tags[M_];
__device__ int   g_len[B_];
__device__ int   g_tagmode;
__device__ int   g_maskmode;

__device__ __forceinline__ float ex2f(float x){ float y; asm("ex2.approx.ftz.f32 %0, %1;" : "=f"(y) : "f"(x)); return y; }
__device__ __forceinline__ float lg2f(float x){ float y; asm("lg2.approx.f32 %0, %1;"     : "=f"(y) : "f"(x)); return y; }
__device__ __forceinline__ float rcpf(float x){ float y; asm("rcp.approx.ftz.f32 %0, %1;" : "=f"(y) : "f"(x)); return y; }

#define CP_ASYNC8(sa, gp)  asm volatile("cp.async.ca.shared.global [%0], [%1], 8;\n"  :: "r"(sa), "l"(gp) : "memory")
#define CP_COMMIT()        asm volatile("cp.async.commit_group;\n" ::: "memory")
#define CP_WAIT(n)         asm volatile("cp.async.wait_group %0;\n" :: "n"(n) : "memory")

// ---------------------------------------------------------------
__global__ void detect_kernel(const unsigned int* __restrict__ tagw,
                              const unsigned char* __restrict__ maskb)
{
    __shared__ int any;
    if (threadIdx.x == 0) any = 0;
    __syncthreads();
    unsigned int w = tagw[2 * threadIdx.x + 1];
    if (w) atomicExch(&any, 1);
    __syncthreads();
    if (threadIdx.x == 0) {
        g_tagmode  = any ? 0 : 1;
        g_maskmode = (maskb[1] != 0) ? 0 : 1;
    }
}

__global__ __launch_bounds__(256)
void convert_kernel(const int* __restrict__ tagsraw,
                    const unsigned char* __restrict__ maskraw)
{
    __shared__ int s_red[8];
    const int b   = blockIdx.x;
    const int tid = threadIdx.x;
    const int tm  = g_tagmode;
    const int mm  = g_maskmode;

    for (int t = tid; t < L_; t += 256) {
        long idx = (long)b * L_ + t;
        g_tags[idx] = (tm == 1) ? tagsraw[2 * idx] : tagsraw[idx];
    }
    int cnt = 0;
    if (mm == 0) {
        const unsigned char* mb = maskraw + (size_t)b * L_;
        for (int t = tid; t < L_; t += 256) cnt += (mb[t] != 0);
    } else {
        const unsigned int* mw = ((const unsigned int*)maskraw) + (size_t)b * L_;
        for (int t = tid; t < L_; t += 256) cnt += (mw[t] != 0);
    }
#pragma unroll
    for (int o = 16; o > 0; o >>= 1) cnt += __shfl_xor_sync(0xffffffffu, cnt, o);
    if ((tid & 31) == 0) s_red[tid >> 5] = cnt;
    __syncthreads();
    if (tid == 0) {
        int s = 0;
#pragma unroll
        for (int i = 0; i < 8; ++i) s += s_red[i];
        g_len[b] = s;
    }
}

// ---------------------------------------------------------------
__global__ void prep_kernel(const float* __restrict__ W, const float* __restrict__ T)
{
    int idx    = blockIdx.x * blockDim.x + threadIdx.x;
    int stride = gridDim.x * blockDim.x;
    for (int i = idx; i < K_*H_; i += stride) {
        int n = i / H_, h = i - n*H_;
        g_Wtf[i] = W[h*K_ + n];
    }
    for (int i = idx; i < K_*K_; i += stride) {
        int j = i >> 6, k = i & 63;
        float t2 = T[k*K_ + j] * LOG2E;
        g_Tt2[i] = t2;
        g_Et[i]  = ex2f(t2 - ESHIFT);
    }
}

// ---------------------------------------------------------------
// GEMM: TF32 mma, cp.async 3-stage pipeline.
// block 128x64, BK=16, 48 k-tiles, 8 warps (4x2), warp tile 32x32.
#define BM      128
#define BK      16
#define NITER   (H_/BK)   // 48
#define PITCH   20        // floats per smem row (bank-conflict-free: (20g+tq)%32 unique)
#define STAGES  3

__global__ __launch_bounds__(256)
void gemm_kernel(const float* __restrict__ F, const float* __restrict__ bias)
{
    __shared__ float As[STAGES][BM * PITCH];
    __shared__ float Bs[STAGES][K_ * PITCH];

    const int tid  = threadIdx.x;
    const int lane = tid & 31;
    const int warp = tid >> 5;
    const int wm   = warp & 3;
    const int wn   = warp >> 2;
    const int rowBase = blockIdx.x * BM;
    const int g  = lane >> 2;
    const int tq = lane & 3;

    // cp.async mapping: 8-byte granules (2 floats)
    // A: 128 rows x 8 chunks; chunks c = tid + 256p, row=c>>3, colf=(c&7)*2
    // B:  64 rows x 8 chunks; chunks c = tid + 256p
    const int aRow0 = tid >> 3;          // rows tid>>3 + 32p
    const int aC    = (tid & 7) * 2;     // float offset in row
    const int bRow0 = tid >> 3;          // 0..31, +32
    // precompute shared byte addresses per stage
    uint32_t sA[STAGES], sB[STAGES];
#pragma unroll
    for (int s = 0; s < STAGES; ++s) {
        sA[s] = (uint32_t)__cvta_generic_to_shared(&As[s][aRow0 * PITCH + aC]);
        sB[s] = (uint32_t)__cvta_generic_to_shared(&Bs[s][bRow0 * PITCH + aC]);
    }
    const float* gA = F      + (size_t)(rowBase + aRow0) * H_ + aC;
    const float* gB = g_Wtf + (size_t)bRow0 * H_ + aC;

    float acc[2][4][4];
#pragma unroll
    for (int mi = 0; mi < 2; ++mi)
#pragma unroll
        for (int ni = 0; ni < 4; ++ni)
#pragma unroll
            for (int q = 0; q < 4; ++q) acc[mi][ni][q] = 0.f;

    // prologue: stages 0,1
#pragma unroll
    for (int s = 0; s < 2; ++s) {
        const int kb = s * BK;
#pragma unroll
        for (int p = 0; p < 4; ++p)
            CP_ASYNC8(sA[s] + p * 32 * PITCH * 4, gA + (size_t)p * 32 * H_ + kb);
#pragma unroll
        for (int p = 0; p < 2; ++p)
            CP_ASYNC8(sB[s] + p * 32 * PITCH * 4, gB + (size_t)p * 32 * H_ + kb);
        CP_COMMIT();
    }

#pragma unroll 1
    for (int k = 0; k < NITER; ++k) {
        const int cur = k % STAGES;
        CP_WAIT(1);              // stage k resident
        __syncthreads();         // stage (k-1)%3 fully consumed by all warps

        if (k + 2 < NITER) {
            const int nxt = (k + 2) % STAGES;
            const int kb  = (k + 2) * BK;
#pragma unroll
            for (int p = 0; p < 4; ++p)
                CP_ASYNC8(sA[nxt] + p * 32 * PITCH * 4, gA + (size_t)p * 32 * H_ + kb);
#pragma unroll
            for (int p = 0; p < 2; ++p)
                CP_ASYNC8(sB[nxt] + p * 32 * PITCH * 4, gB + (size_t)p * 32 * H_ + kb);
        }
        CP_COMMIT();

        const float* A0 = As[cur];
        const float* B0 = Bs[cur];
#pragma unroll
        for (int ks = 0; ks < 2; ++ks) {
            const int c0 = ks * 8 + tq;
            uint32_t afr[2][4], bfr[4][2];
#pragma unroll
            for (int mi = 0; mi < 2; ++mi) {
                int r = wm * 32 + mi * 16 + g;
                afr[mi][0] = __float_as_uint(A0[ r      * PITCH + c0    ]);
                afr[mi][1] = __float_as_uint(A0[(r + 8) * PITCH + c0    ]);
                afr[mi][2] = __float_as_uint(A0[ r      * PITCH + c0 + 4]);
                afr[mi][3] = __float_as_uint(A0[(r + 8) * PITCH + c0 + 4]);
            }
#pragma unroll
            for (int ni = 0; ni < 4; ++ni) {
                int n = wn * 32 + ni * 8 + g;
                bfr[ni][0] = __float_as_uint(B0[n * PITCH + c0    ]);
                bfr[ni][1] = __float_as_uint(B0[n * PITCH + c0 + 4]);
            }
#pragma unroll
            for (int mi = 0; mi < 2; ++mi)
#pragma unroll
                for (int ni = 0; ni < 4; ++ni) {
                    asm volatile(
                        "mma.sync.aligned.m16n8k8.row.col.f32.tf32.tf32.f32 "
                        "{%0,%1,%2,%3}, {%4,%5,%6,%7}, {%8,%9}, {%0,%1,%2,%3};"
                        : "+f"(acc[mi][ni][0]), "+f"(acc[mi][ni][1]),
                          "+f"(acc[mi][ni][2]), "+f"(acc[mi][ni][3])
                        : "r"(afr[mi][0]), "r"(afr[mi][1]), "r"(afr[mi][2]), "r"(afr[mi][3]),
                          "r"(bfr[ni][0]), "r"(bfr[ni][1]));
                }
        }
        __syncthreads();   // protect stage cur from overwrite at k+3
    }

    // epilogue: +bias, *log2e
#pragma unroll
    for (int mi = 0; mi < 2; ++mi) {
#pragma unroll
        for (int ni = 0; ni < 4; ++ni) {
            int col = wn * 32 + ni * 8 + tq * 2;
            float b0 = bias[col], b1 = bias[col + 1];
            int r0 = rowBase + wm * 32 + mi * 16 + g;
            float2 v0 = make_float2((acc[mi][ni][0] + b0) * LOG2E,
                                    (acc[mi][ni][1] + b1) * LOG2E);
            float2 v1 = make_float2((acc[mi][ni][2] + b0) * LOG2E,
                                    (acc[mi][ni][3] + b1) * LOG2E);
            *reinterpret_cast<float2*>(&g_emit2[(size_t) r0      * K_ + col]) = v0;
            *reinterpret_cast<float2*>(&g_emit2[(size_t)(r0 + 8) * K_ + col]) = v1;
        }
    }
}

// ---------------------------------------------------------------
// CRF forward in linear domain + gold score.
// 128 threads/batch: j = tid>>1 output state, half = tid&1 covers 32 sources.
__global__ __launch_bounds__(128)
void crf_kernel(float* __restrict__ out)
{
    __shared__ float ds[2][K_];
    __shared__ float s_red[4];

    int bid = blockIdx.x;
    int b   = (bid < 148) ? bid : (255 - (bid - 148));

    const int tid  = threadIdx.x;
    const int lane = tid & 31;
    const int wid  = tid >> 5;
    const int j    = tid >> 1;
    const int half = tid & 1;

    const int len = g_len[b];

    // ---- gold path score ----
    const int*   tg = g_tags + (size_t)b * L_;
    const float* eb = g_emit2 + (size_t)b * L_ * K_;
    float sc = 0.f;
    for (int t = tid; t < len; t += 128) {
        int kt = tg[t];
        sc += eb[t * K_ + kt];
        if (t >= 1) sc += g_Tt2[kt * K_ + tg[t - 1]];
    }
#pragma unroll
    for (int o = 16; o > 0; o >>= 1) sc += __shfl_xor_sync(0xffffffffu, sc, o);
    if (lane == 0) s_red[wid] = sc;
    __syncthreads();
    const float score = (s_red[0] + s_red[1]) + (s_red[2] + s_red[3]);

    // ---- E rows in registers ----
    float Erow[32];
    {
        const float4* tp = reinterpret_cast<const float4*>(g_Et + j * K_ + half * 32);
#pragma unroll
        for (int q = 0; q < 8; ++q) {
            float4 v = tp[q];
            Erow[4*q] = v.x; Erow[4*q+1] = v.y; Erow[4*q+2] = v.z; Erow[4*q+3] = v.w;
        }
    }

    // ---- init + deep emit prefetch (4 steps) ----
    if (half == 0) ds[0][j] = ex2f(eb[j]);
    float C = 0.f;
    float ebuf[4];
#pragma unroll
    for (int q = 0; q < 4; ++q) ebuf[q] = eb[(1 + q) * K_ + j];   // len >= 128 > 5
    __syncthreads();

    int cur = 0;
    for (int t = 1; t < len; ++t) {
        const int slot = (t - 1) & 3;
        const float se = ex2f(ebuf[slot]);
        int tn = t + 4; if (tn > L_ - 1) tn = L_ - 1;
        ebuf[slot] = eb[tn * K_ + j];                 // refill, 4 steps of latency cover

        const float4* p4 = reinterpret_cast<const float4*>(&ds[cur][half * 32]);
        float aa[8];
#pragma unroll
        for (int q = 0; q < 8; ++q) {
            float4 v = p4[q];
            aa[q] = fmaf(v.w, Erow[4*q+3],
                    fmaf(v.z, Erow[4*q+2],
                    fmaf(v.y, Erow[4*q+1], v.x * Erow[4*q])));
        }
        float acc = ((aa[0]+aa[1]) + (aa[2]+aa[3])) + ((aa[4]+aa[5]) + (aa[6]+aa[7]));
        acc += __shfl_xor_sync(0xffffffffu, acc, 1);
        float dn = acc * se;

        if ((t & 7) == 0) {
            float m = dn;
#pragma unroll
            for (int o = 16; o > 0; o >>= 1) m = fmaxf(m, __shfl_xor_sync(0xffffffffu, m, o));
            if (lane == 0) s_red[wid] = m;
            __syncthreads();
            m = fmaxf(fmaxf(s_red[0], s_red[1]), fmaxf(s_red[2], s_red[3]));
            m = fmaxf(m, 1e-30f);
            dn *= rcpf(m);
            C += lg2f(m);
        }
        if (half == 0) ds[cur ^ 1][j] = dn;
        __syncthreads();
        cur ^= 1;
    }

    // ---- final logsumexp ----
    float v = (half == 0) ? ds[cur][j] : 0.f;
#pragma unroll
    for (int o = 16; o > 0; o >>= 1) v += __shfl_xor_sync(0xffffffffu, v, o);
    if (lane == 0) s_red[wid] = v;
    __syncthreads();
    const float S = (s_red[0] + s_red[1]) + (s_red[2] + s_red[3]);

    const float logz2 = C + ESHIFT * (float)(len - 1) + lg2f(S);
    if (tid == 0) out[b] = (logz2 - score) * LN2;
}

// ---------------------------------------------------------------
extern "C" void kernel_launch(void* const* d_in, const int* in_sizes, int n_in,
                              void* d_out, int out_size)
{
    const float*         features = (const float*)d_in[0];
    const float*         W        = (const float*)d_in[1];
    const float*         bias     = (const float*)d_in[2];
    const float*         trans    = (const float*)d_in[3];
    const int*           tagsraw  = (const int*)d_in[4];
    const unsigned char* maskraw  = (const unsigned char*)d_in[5];
    float*               out      = (float*)d_out;

    detect_kernel<<<1, 256>>>((const unsigned int*)tagsraw, maskraw);
    convert_kernel<<<B_, 256>>>(tagsraw, maskraw);
    prep_kernel<<<192, 256>>>(W, trans);
    gemm_kernel<<<M_ / BM, 256>>>(features, bias);
    crf_kernel<<<B_, 128>>>(out);
}

// round 5
// speedup vs baseline: 2.1447x; 2.1447x over previous
#include <cuda_runtime.h>
#include <cuda_bf16.h>
#include <cstdint>

#define B_ 256
#define L_ 512
#define H_ 768
#define K_ 64
#define M_ (B_*L_)

#define LOG2E 1.4426950408889634f
#define LN2   0.6931471805599453f
#define ESHIFT 6.0f

// -------- device scratch --------
__device__ float          g_emit2[M_*K_];     // emit * log2(e)
__device__ float          g_Tt2[K_*K_];       // Tt2[j][k] = T[k][j]*log2e (gold score)
__device__ float          g_Et[K_*K_];        // Et[j][i]  = 2^(T[i][j]*log2e - 6)
__device__ __nv_bfloat16  g_Wt[K_*H_];        // W^T bf16 [n][h]
__device__ int            g_tags[M_];
__device__ int            g_len[B_];
__device__ int            g_tagmode;
__device__ int            g_maskmode;

__device__ __forceinline__ float ex2f(float x){ float y; asm("ex2.approx.ftz.f32 %0, %1;" : "=f"(y) : "f"(x)); return y; }
__device__ __forceinline__ float lg2f(float x){ float y; asm("lg2.approx.f32 %0, %1;"     : "=f"(y) : "f"(x)); return y; }
__device__ __forceinline__ float rcpf(float x){ float y; asm("rcp.approx.ftz.f32 %0, %1;" : "=f"(y) : "f"(x)); return y; }

// ---------------------------------------------------------------
__global__ void detect_kernel(const unsigned int* __restrict__ tagw,
                              const unsigned char* __restrict__ maskb)
{
    __shared__ int any;
    if (threadIdx.x == 0) any = 0;
    __syncthreads();
    unsigned int w = tagw[2 * threadIdx.x + 1];
    if (w) atomicExch(&any, 1);
    __syncthreads();
    if (threadIdx.x == 0) {
        g_tagmode  = any ? 0 : 1;
        g_maskmode = (maskb[1] != 0) ? 0 : 1;
    }
}

__global__ __launch_bounds__(256)
void convert_kernel(const int* __restrict__ tagsraw,
                    const unsigned char* __restrict__ maskraw)
{
    __shared__ int s_red[8];
    const int b   = blockIdx.x;
    const int tid = threadIdx.x;
    const int tm  = g_tagmode;
    const int mm  = g_maskmode;

    for (int t = tid; t < L_; t += 256) {
        long idx = (long)b * L_ + t;
        g_tags[idx] = (tm == 1) ? tagsraw[2 * idx] : tagsraw[idx];
    }
    int cnt = 0;
    if (mm == 0) {
        const unsigned char* mb = maskraw + (size_t)b * L_;
        for (int t = tid; t < L_; t += 256) cnt += (mb[t] != 0);
    } else {
        const unsigned int* mw = ((const unsigned int*)maskraw) + (size_t)b * L_;
        for (int t = tid; t < L_; t += 256) cnt += (mw[t] != 0);
    }
#pragma unroll
    for (int o = 16; o > 0; o >>= 1) cnt += __shfl_xor_sync(0xffffffffu, cnt, o);
    if ((tid & 31) == 0) s_red[tid >> 5] = cnt;
    __syncthreads();
    if (tid == 0) {
        int s = 0;
#pragma unroll
        for (int i = 0; i < 8; ++i) s += s_red[i];
        g_len[b] = s;
    }
}

// ---------------------------------------------------------------
__global__ void prep_kernel(const float* __restrict__ W, const float* __restrict__ T)
{
    int idx    = blockIdx.x * blockDim.x + threadIdx.x;
    int stride = gridDim.x * blockDim.x;
    for (int i = idx; i < K_*H_; i += stride) {
        int n = i / H_, h = i - n*H_;
        g_Wt[i] = __float2bfloat16(W[h*K_ + n]);
    }
    for (int i = idx; i < K_*K_; i += stride) {
        int j = i >> 6, k = i & 63;
        float t2 = T[k*K_ + j] * LOG2E;
        g_Tt2[i] = t2;
        g_Et[i]  = ex2f(t2 - ESHIFT);
    }
}

// ---------------------------------------------------------------
// GEMM (R3-proven): bf16 HMMA, 2-stage smem double buffer + register prefetch
#define BM     128
#define BK     32
#define NITER  (H_/BK)   // 24
#define APITCH 40

__global__ __launch_bounds__(256)
void gemm_kernel(const float* __restrict__ F, const float* __restrict__ bias)
{
    __shared__ __nv_bfloat16 Ash[2][BM * APITCH];
    __shared__ __nv_bfloat16 Bsh[2][K_ * APITCH];

    const int tid  = threadIdx.x;
    const int lane = tid & 31;
    const int warp = tid >> 5;
    const int wm   = warp & 3;
    const int wn   = warp >> 2;
    const int rowBase = blockIdx.x * BM;

    float acc[2][4][4];
#pragma unroll
    for (int mi = 0; mi < 2; ++mi)
#pragma unroll
        for (int ni = 0; ni < 4; ++ni)
#pragma unroll
            for (int q = 0; q < 4; ++q) acc[mi][ni][q] = 0.f;

    const int aRow = tid >> 3;
    const int aKv  = tid & 7;
    const int bN   = tid >> 2;
    const int bKv  = tid & 3;
    const int g  = lane >> 2;
    const int tq = lane & 3;

    float4 av[4];
    int4   bv;

#pragma unroll
    for (int p = 0; p < 4; ++p)
        av[p] = *reinterpret_cast<const float4*>(
            F + (size_t)(rowBase + aRow + p*32) * H_ + aKv * 4);
    bv = *reinterpret_cast<const int4*>(g_Wt + bN*H_ + bKv*8);

#pragma unroll 1
    for (int k = 0; k < NITER; ++k) {
        const int cur = k & 1;
#pragma unroll
        for (int p = 0; p < 4; ++p) {
            int r = aRow + p * 32;
            __nv_bfloat162 h0 = __floats2bfloat162_rn(av[p].x, av[p].y);
            __nv_bfloat162 h1 = __floats2bfloat162_rn(av[p].z, av[p].w);
            *reinterpret_cast<__nv_bfloat162*>(&Ash[cur][r*APITCH + aKv*4    ]) = h0;
            *reinterpret_cast<__nv_bfloat162*>(&Ash[cur][r*APITCH + aKv*4 + 2]) = h1;
        }
        *reinterpret_cast<int4*>(&Bsh[cur][bN*APITCH + bKv*8]) = bv;
        __syncthreads();

        if (k + 1 < NITER) {
            const int kb = (k + 1) * BK;
#pragma unroll
            for (int p = 0; p < 4; ++p)
                av[p] = *reinterpret_cast<const float4*>(
                    F + (size_t)(rowBase + aRow + p*32) * H_ + kb + aKv * 4);
            bv = *reinterpret_cast<const int4*>(g_Wt + bN*H_ + kb + bKv*8);
        }

#pragma unroll
        for (int ks = 0; ks < 2; ++ks) {
            uint32_t afr[2][4], bfr[4][2];
            const int c = ks*16 + tq*2;
#pragma unroll
            for (int mi = 0; mi < 2; ++mi) {
                int r = wm*32 + mi*16 + g;
                afr[mi][0] = *reinterpret_cast<const uint32_t*>(&Ash[cur][ r     *APITCH + c    ]);
                afr[mi][1] = *reinterpret_cast<const uint32_t*>(&Ash[cur][(r + 8)*APITCH + c    ]);
                afr[mi][2] = *reinterpret_cast<const uint32_t*>(&Ash[cur][ r     *APITCH + c + 8]);
                afr[mi][3] = *reinterpret_cast<const uint32_t*>(&Ash[cur][(r + 8)*APITCH + c + 8]);
            }
#pragma unroll
            for (int ni = 0; ni < 4; ++ni) {
                int n = wn*32 + ni*8 + g;
                bfr[ni][0] = *reinterpret_cast<const uint32_t*>(&Bsh[cur][n*APITCH + c    ]);
                bfr[ni][1] = *reinterpret_cast<const uint32_t*>(&Bsh[cur][n*APITCH + c + 8]);
            }
#pragma unroll
            for (int mi = 0; mi < 2; ++mi)
#pragma unroll
                for (int ni = 0; ni < 4; ++ni) {
                    asm volatile(
                        "mma.sync.aligned.m16n8k16.row.col.f32.bf16.bf16.f32 "
                        "{%0,%1,%2,%3}, {%4,%5,%6,%7}, {%8,%9}, {%0,%1,%2,%3};"
                        : "+f"(acc[mi][ni][0]), "+f"(acc[mi][ni][1]),
                          "+f"(acc[mi][ni][2]), "+f"(acc[mi][ni][3])
                        : "r"(afr[mi][0]), "r"(afr[mi][1]), "r"(afr[mi][2]), "r"(afr[mi][3]),
                          "r"(bfr[ni][0]), "r"(bfr[ni][1]));
                }
        }
        __syncthreads();
    }

#pragma unroll
    for (int mi = 0; mi < 2; ++mi) {
#pragma unroll
        for (int ni = 0; ni < 4; ++ni) {
            int col = wn*32 + ni*8 + tq*2;
            float b0 = bias[col], b1 = bias[col + 1];
            int r0 = rowBase + wm*32 + mi*16 + g;
            float2 v0 = make_float2((acc[mi][ni][0] + b0) * LOG2E,
                                    (acc[mi][ni][1] + b1) * LOG2E);
            float2 v1 = make_float2((acc[mi][ni][2] + b0) * LOG2E,
                                    (acc[mi][ni][3] + b1) * LOG2E);
            *reinterpret_cast<float2*>(&g_emit2[(size_t) r0      * K_ + col]) = v0;
            *reinterpret_cast<float2*>(&g_emit2[(size_t)(r0 + 8) * K_ + col]) = v1;
        }
    }
}

// ---------------------------------------------------------------
// CRF forward, linear domain. 128 threads/batch: j = tid>>1, half = tid&1.
// Emit prefetch ring of 8 with COMPILE-TIME slots (loop unrolled in chunks
// of 8). Renorm every 8 steps using the d-values already loaded for the
// matvec (local fmax tree + 1 shfl) — no shared round-trip, no extra barrier.
__global__ __launch_bounds__(128)
void crf_kernel(float* __restrict__ out)
{
    __shared__ float ds[2][K_];
    __shared__ float s_red[4];

    int bid = blockIdx.x;
    int b   = (bid < 148) ? bid : (255 - (bid - 148));   // long/short pairing

    const int tid  = threadIdx.x;
    const int lane = tid & 31;
    const int wid  = tid >> 5;
    const int j    = tid >> 1;
    const int half = tid & 1;

    const int len = g_len[b];

    // ---- gold path score ----
    const int*   tg = g_tags + (size_t)b * L_;
    const float* eb = g_emit2 + (size_t)b * L_ * K_;
    float sc = 0.f;
    for (int t = tid; t < len; t += 128) {
        int kt = tg[t];
        sc += eb[t * K_ + kt];
        if (t >= 1) sc += g_Tt2[kt * K_ + tg[t - 1]];
    }
#pragma unroll
    for (int o = 16; o > 0; o >>= 1) sc += __shfl_xor_sync(0xffffffffu, sc, o);
    if (lane == 0) s_red[wid] = sc;
    __syncthreads();
    const float score = (s_red[0] + s_red[1]) + (s_red[2] + s_red[3]);

    // ---- E rows in registers ----
    float Erow[32];
    {
        const float4* tp = reinterpret_cast<const float4*>(g_Et + j * K_ + half * 32);
#pragma unroll
        for (int q = 0; q < 8; ++q) {
            float4 v = tp[q];
            Erow[4*q] = v.x; Erow[4*q+1] = v.y; Erow[4*q+2] = v.z; Erow[4*q+3] = v.w;
        }
    }

    // ---- init + 8-deep emit prefetch ring (slot (t-1)&7 holds emit for t) ----
    if (half == 0) ds[0][j] = ex2f(eb[j]);
    float C = 0.f;
    float ebuf[8];
#pragma unroll
    for (int q = 0; q < 8; ++q) ebuf[q] = eb[(q + 1) * K_ + j];   // len >= 128
    __syncthreads();

    int cur = 0;

    // one recursion step; slot/renorm/use_ring are compile-time at call sites
    auto STEP = [&](int t, int slot, bool renorm, bool use_ring) {
        float ev;
        if (use_ring) {
            ev = ebuf[slot];
            int tn = t + 8; if (tn > L_ - 1) tn = L_ - 1;
            ebuf[slot] = eb[tn * K_ + j];                 // refill, 8-step cover
        } else {
            ev = eb[t * K_ + j];
        }
        const float se = ex2f(ev);

        const float4* p4 = reinterpret_cast<const float4*>(&ds[cur][half * 32]);
        float4 vv[8];
#pragma unroll
        for (int q = 0; q < 8; ++q) vv[q] = p4[q];

        float aa[8];
#pragma unroll
        for (int q = 0; q < 8; ++q) {
            aa[q] = fmaf(vv[q].w, Erow[4*q+3],
                    fmaf(vv[q].z, Erow[4*q+2],
                    fmaf(vv[q].y, Erow[4*q+1], vv[q].x * Erow[4*q])));
        }
        float acc = ((aa[0]+aa[1]) + (aa[2]+aa[3])) + ((aa[4]+aa[5]) + (aa[6]+aa[7]));
        acc += __shfl_xor_sync(0xffffffffu, acc, 1);      // combine halves
        float dn = acc * se;

        if (renorm) {
            // block max of d_{t-1} from values already in registers
            float m0 = fmaxf(fmaxf(vv[0].x, vv[0].y), fmaxf(vv[0].z, vv[0].w));
            float m1 = fmaxf(fmaxf(vv[1].x, vv[1].y), fmaxf(vv[1].z, vv[1].w));
            float m2 = fmaxf(fmaxf(vv[2].x, vv[2].y), fmaxf(vv[2].z, vv[2].w));
            float m3 = fmaxf(fmaxf(vv[3].x, vv[3].y), fmaxf(vv[3].z, vv[3].w));
            float m4 = fmaxf(fmaxf(vv[4].x, vv[4].y), fmaxf(vv[4].z, vv[4].w));
            float m5 = fmaxf(fmaxf(vv[5].x, vv[5].y), fmaxf(vv[5].z, vv[5].w));
            float m6 = fmaxf(fmaxf(vv[6].x, vv[6].y), fmaxf(vv[6].z, vv[6].w));
            float m7 = fmaxf(fmaxf(vv[7].x, vv[7].y), fmaxf(vv[7].z, vv[7].w));
            float m = fmaxf(fmaxf(fmaxf(m0, m1), fmaxf(m2, m3)),
                            fmaxf(fmaxf(m4, m5), fmaxf(m6, m7)));
            m = fmaxf(m, __shfl_xor_sync(0xffffffffu, m, 1));  // full 64-state max
            m = fmaxf(m, 1e-30f);
            dn *= rcpf(m);
            C += lg2f(m);
        }
        if (half == 0) ds[cur ^ 1][j] = dn;
        __syncthreads();
        cur ^= 1;
    };

    // head peel t=1..7 (always < len since len >= 128)
#pragma unroll
    for (int t = 1; t <= 7; ++t) STEP(t, t - 1, false, true);

    // main chunks of 8; t = tb+i, slot (i+7)&7, renorm at t % 8 == 0 (i==0)
    int tb = 8;
    for (; tb + 8 <= len; tb += 8) {
#pragma unroll
        for (int i = 0; i < 8; ++i)
            STEP(tb + i, (i + 7) & 7, i == 0, true);
    }
    // tail (< 8 steps): direct emit loads, no ring (keeps ring static-indexed)
    for (int t = tb; t < len; ++t)
        STEP(t, 0, (t & 7) == 0, false);

    // ---- final logsumexp ----
    float v = (half == 0) ? ds[cur][j] : 0.f;
#pragma unroll
    for (int o = 16; o > 0; o >>= 1) v += __shfl_xor_sync(0xffffffffu, v, o);
    if (lane == 0) s_red[wid] = v;
    __syncthreads();
    const float S = (s_red[0] + s_red[1]) + (s_red[2] + s_red[3]);

    const float logz2 = C + ESHIFT * (float)(len - 1) + lg2f(S);
    if (tid == 0) out[b] = (logz2 - score) * LN2;
}

// ---------------------------------------------------------------
extern "C" void kernel_launch(void* const* d_in, const int* in_sizes, int n_in,
                              void* d_out, int out_size)
{
    const float*         features = (const float*)d_in[0];
    const float*         W        = (const float*)d_in[1];
    const float*         bias     = (const float*)d_in[2];
    const float*         trans    = (const float*)d_in[3];
    const int*           tagsraw  = (const int*)d_in[4];
    const unsigned char* maskraw  = (const unsigned char*)d_in[5];
    float*               out      = (float*)d_out;

    detect_kernel<<<1, 256>>>((const unsigned int*)tagsraw, maskraw);
    convert_kernel<<<B_, 256>>>(tagsraw, maskraw);
    prep_kernel<<<192, 256>>>(W, trans);
    gemm_kernel<<<M_ / BM, 256>>>(features, bias);
    crf_kernel<<<B_, 128>>>(out);
}

// round 6
// speedup vs baseline: 2.6619x; 1.2412x over previous
#include <cuda_runtime.h>
#include <cuda_bf16.h>
#include <cstdint>

#define B_ 256
#define L_ 512
#define H_ 768
#define K_ 64
#define M_ (B_*L_)

#define LOG2E 1.4426950408889634f
#define LN2   0.6931471805599453f
#define ESHIFT 6.0f

// -------- device scratch --------
__device__ float          g_emit2[M_*K_];     // emit * log2(e)
__device__ float          g_Tt2[K_*K_];       // Tt2[j][k] = T[k][j]*log2e (gold score)
__device__ float          g_Et[K_*K_];        // Et[j][i]  = 2^(T[i][j]*log2e - 6)
__device__ __nv_bfloat16  g_Wt[K_*H_];        // W^T bf16 [n][h]
__device__ int            g_tags[M_];
__device__ int            g_len[B_];
__device__ int            g_cnt[B_];          // per-batch tile completion counter
__device__ int            g_tagmode;
__device__ int            g_maskmode;

__device__ __forceinline__ float ex2f(float x){ float y; asm("ex2.approx.ftz.f32 %0, %1;" : "=f"(y) : "f"(x)); return y; }
__device__ __forceinline__ float lg2f(float x){ float y; asm("lg2.approx.f32 %0, %1;"     : "=f"(y) : "f"(x)); return y; }
__device__ __forceinline__ float rcpf(float x){ float y; asm("rcp.approx.ftz.f32 %0, %1;" : "=f"(y) : "f"(x)); return y; }
#define BAR64() asm volatile("bar.sync 1, 64;" ::: "memory")

// ---------------------------------------------------------------
__global__ void detect_kernel(const unsigned int* __restrict__ tagw,
                              const unsigned char* __restrict__ maskb)
{
    __shared__ int any;
    if (threadIdx.x == 0) any = 0;
    __syncthreads();
    unsigned int w = tagw[2 * threadIdx.x + 1];
    if (w) atomicExch(&any, 1);
    __syncthreads();
    if (threadIdx.x == 0) {
        g_tagmode  = any ? 0 : 1;
        g_maskmode = (maskb[1] != 0) ? 0 : 1;
    }
}

__global__ __launch_bounds__(256)
void convert_kernel(const int* __restrict__ tagsraw,
                    const unsigned char* __restrict__ maskraw)
{
    __shared__ int s_red[8];
    const int b   = blockIdx.x;
    const int tid = threadIdx.x;
    const int tm  = g_tagmode;
    const int mm  = g_maskmode;

    if (tid == 0) g_cnt[b] = 0;            // reset handoff counters every call

    for (int t = tid; t < L_; t += 256) {
        long idx = (long)b * L_ + t;
        g_tags[idx] = (tm == 1) ? tagsraw[2 * idx] : tagsraw[idx];
    }
    int cnt = 0;
    if (mm == 0) {
        const unsigned char* mb = maskraw + (size_t)b * L_;
        for (int t = tid; t < L_; t += 256) cnt += (mb[t] != 0);
    } else {
        const unsigned int* mw = ((const unsigned int*)maskraw) + (size_t)b * L_;
        for (int t = tid; t < L_; t += 256) cnt += (mw[t] != 0);
    }
#pragma unroll
    for (int o = 16; o > 0; o >>= 1) cnt += __shfl_xor_sync(0xffffffffu, cnt, o);
    if ((tid & 31) == 0) s_red[tid >> 5] = cnt;
    __syncthreads();
    if (tid == 0) {
        int s = 0;
#pragma unroll
        for (int i = 0; i < 8; ++i) s += s_red[i];
        g_len[b] = s;
    }
}

// ---------------------------------------------------------------
__global__ void prep_kernel(const float* __restrict__ W, const float* __restrict__ T)
{
    int idx    = blockIdx.x * blockDim.x + threadIdx.x;
    int stride = gridDim.x * blockDim.x;
    for (int i = idx; i < K_*H_; i += stride) {
        int n = i / H_, h = i - n*H_;
        g_Wt[i] = __float2bfloat16(W[h*K_ + n]);
    }
    for (int i = idx; i < K_*K_; i += stride) {
        int j = i >> 6, k = i & 63;
        float t2 = T[k*K_ + j] * LOG2E;
        g_Tt2[i] = t2;
        g_Et[i]  = ex2f(t2 - ESHIFT);
    }
}

// ---------------------------------------------------------------
// FUSED kernel: GEMM tile (blocks 4b..4b+3 cover batch b), then the block
// that completes the batch's 4th tile runs the CRF for that batch in-place.
#define BM     128
#define BK     32
#define NITER  (H_/BK)   // 24
#define APITCH 40

__global__ __launch_bounds__(256)
void fused_kernel(const float* __restrict__ F, const float* __restrict__ bias,
                  float* __restrict__ out)
{
    __shared__ __nv_bfloat16 Ash[2][BM * APITCH];
    __shared__ __nv_bfloat16 Bsh[2][K_ * APITCH];
    __shared__ float s_red[8];
    __shared__ float ds[2][K_];
    __shared__ float s_score;
    __shared__ int   s_owner;

    const int tid  = threadIdx.x;
    const int lane = tid & 31;
    const int warp = tid >> 5;
    const int wm   = warp & 3;
    const int wn   = warp >> 2;
    const int rowBase = blockIdx.x * BM;

    // ================= GEMM phase =================
    {
        float acc[2][4][4];
#pragma unroll
        for (int mi = 0; mi < 2; ++mi)
#pragma unroll
            for (int ni = 0; ni < 4; ++ni)
#pragma unroll
                for (int q = 0; q < 4; ++q) acc[mi][ni][q] = 0.f;

        const int aRow = tid >> 3;
        const int aKv  = tid & 7;
        const int bN   = tid >> 2;
        const int bKv  = tid & 3;
        const int g  = lane >> 2;
        const int tq = lane & 3;

        float4 av[4];
        int4   bv;
#pragma unroll
        for (int p = 0; p < 4; ++p)
            av[p] = *reinterpret_cast<const float4*>(
                F + (size_t)(rowBase + aRow + p*32) * H_ + aKv * 4);
        bv = *reinterpret_cast<const int4*>(g_Wt + bN*H_ + bKv*8);

#pragma unroll 1
        for (int k = 0; k < NITER; ++k) {
            const int cur = k & 1;
#pragma unroll
            for (int p = 0; p < 4; ++p) {
                int r = aRow + p * 32;
                __nv_bfloat162 h0 = __floats2bfloat162_rn(av[p].x, av[p].y);
                __nv_bfloat162 h1 = __floats2bfloat162_rn(av[p].z, av[p].w);
                *reinterpret_cast<__nv_bfloat162*>(&Ash[cur][r*APITCH + aKv*4    ]) = h0;
                *reinterpret_cast<__nv_bfloat162*>(&Ash[cur][r*APITCH + aKv*4 + 2]) = h1;
            }
            *reinterpret_cast<int4*>(&Bsh[cur][bN*APITCH + bKv*8]) = bv;
            __syncthreads();

            if (k + 1 < NITER) {
                const int kb = (k + 1) * BK;
#pragma unroll
                for (int p = 0; p < 4; ++p)
                    av[p] = *reinterpret_cast<const float4*>(
                        F + (size_t)(rowBase + aRow + p*32) * H_ + kb + aKv * 4);
                bv = *reinterpret_cast<const int4*>(g_Wt + bN*H_ + kb + bKv*8);
            }

#pragma unroll
            for (int ks = 0; ks < 2; ++ks) {
                uint32_t afr[2][4], bfr[4][2];
                const int c = ks*16 + tq*2;
#pragma unroll
                for (int mi = 0; mi < 2; ++mi) {
                    int r = wm*32 + mi*16 + g;
                    afr[mi][0] = *reinterpret_cast<const uint32_t*>(&Ash[cur][ r     *APITCH + c    ]);
                    afr[mi][1] = *reinterpret_cast<const uint32_t*>(&Ash[cur][(r + 8)*APITCH + c    ]);
                    afr[mi][2] = *reinterpret_cast<const uint32_t*>(&Ash[cur][ r     *APITCH + c + 8]);
                    afr[mi][3] = *reinterpret_cast<const uint32_t*>(&Ash[cur][(r + 8)*APITCH + c + 8]);
                }
#pragma unroll
                for (int ni = 0; ni < 4; ++ni) {
                    int n = wn*32 + ni*8 + g;
                    bfr[ni][0] = *reinterpret_cast<const uint32_t*>(&Bsh[cur][n*APITCH + c    ]);
                    bfr[ni][1] = *reinterpret_cast<const uint32_t*>(&Bsh[cur][n*APITCH + c + 8]);
                }
#pragma unroll
                for (int mi = 0; mi < 2; ++mi)
#pragma unroll
                    for (int ni = 0; ni < 4; ++ni) {
                        asm volatile(
                            "mma.sync.aligned.m16n8k16.row.col.f32.bf16.bf16.f32 "
                            "{%0,%1,%2,%3}, {%4,%5,%6,%7}, {%8,%9}, {%0,%1,%2,%3};"
                            : "+f"(acc[mi][ni][0]), "+f"(acc[mi][ni][1]),
                              "+f"(acc[mi][ni][2]), "+f"(acc[mi][ni][3])
                            : "r"(afr[mi][0]), "r"(afr[mi][1]), "r"(afr[mi][2]), "r"(afr[mi][3]),
                              "r"(bfr[ni][0]), "r"(bfr[ni][1]));
                    }
            }
            __syncthreads();
        }

#pragma unroll
        for (int mi = 0; mi < 2; ++mi) {
#pragma unroll
            for (int ni = 0; ni < 4; ++ni) {
                int col = wn*32 + ni*8 + tq*2;
                float b0 = bias[col], b1 = bias[col + 1];
                int r0 = rowBase + wm*32 + mi*16 + g;
                float2 v0 = make_float2((acc[mi][ni][0] + b0) * LOG2E,
                                        (acc[mi][ni][1] + b1) * LOG2E);
                float2 v1 = make_float2((acc[mi][ni][2] + b0) * LOG2E,
                                        (acc[mi][ni][3] + b1) * LOG2E);
                *reinterpret_cast<float2*>(&g_emit2[(size_t) r0      * K_ + col]) = v0;
                *reinterpret_cast<float2*>(&g_emit2[(size_t)(r0 + 8) * K_ + col]) = v1;
            }
        }
    }

    // ================= handoff =================
    const int b = blockIdx.x >> 2;
    __threadfence();                 // release: publish this block's emit tile
    __syncthreads();                 // all threads' stores+fences done
    if (tid == 0) s_owner = (atomicAdd(&g_cnt[b], 1) == 3);
    __syncthreads();
    if (!s_owner) return;
    __threadfence();                 // acquire: other quad blocks' tiles visible

    // ================= CRF phase (owner block only) =================
    const int len = g_len[b];
    const int*   tg = g_tags + (size_t)b * L_;
    const float* eb = g_emit2 + (size_t)b * L_ * K_;

    // ---- gold path score with all 256 threads ----
    {
        float sc = 0.f;
        for (int t = tid; t < len; t += 256) {
            int kt = tg[t];
            sc += eb[t * K_ + kt];
            if (t >= 1) sc += g_Tt2[kt * K_ + tg[t - 1]];
        }
#pragma unroll
        for (int o = 16; o > 0; o >>= 1) sc += __shfl_xor_sync(0xffffffffu, sc, o);
        if (lane == 0) s_red[warp] = sc;
        __syncthreads();
        if (tid == 0) {
            float s = 0.f;
#pragma unroll
            for (int i = 0; i < 8; ++i) s += s_red[i];
            s_score = s;
        }
        __syncthreads();
    }

    if (tid >= 64) return;           // recursion: warps 0-1 only (bar.sync 1,64)
    const int j = tid;

    // ---- all 64 E coefficients in registers: Erow[i] = 2^(T2[i][j]-6) ----
    float Erow[64];
    {
        const float4* ep = reinterpret_cast<const float4*>(g_Et + j * K_);
#pragma unroll
        for (int q = 0; q < 16; ++q) {
            float4 v = ep[q];
            Erow[4*q] = v.x; Erow[4*q+1] = v.y; Erow[4*q+2] = v.z; Erow[4*q+3] = v.w;
        }
    }

    ds[0][j] = ex2f(eb[j]);
    float C = 0.f;
    float ebuf[8];
#pragma unroll
    for (int q = 0; q < 8; ++q) ebuf[q] = eb[(q + 1) * K_ + j];   // len >= 128
    BAR64();

    int cur = 0;

    auto STEP = [&](int t, int slot, bool renorm, bool use_ring) {
        float ev;
        if (use_ring) {
            ev = ebuf[slot];
            int tn = t + 8; if (tn > L_ - 1) tn = L_ - 1;
            ebuf[slot] = eb[tn * K_ + j];
        } else {
            ev = eb[t * K_ + j];
        }
        const float se = ex2f(ev);

        const float4* p4 = reinterpret_cast<const float4*>(ds[cur]);  // broadcast reads
        float a0=0.f,a1=0.f,a2=0.f,a3=0.f,a4=0.f,a5=0.f,a6=0.f,a7=0.f;
        float mA = 0.f, mB = 0.f;    // streaming max (d-values are >= 0 in linear domain)
#pragma unroll
        for (int q = 0; q < 16; ++q) {
            float4 v = p4[q];
            if (q & 1) {
                a4 = fmaf(v.x, Erow[4*q    ], a4);
                a5 = fmaf(v.y, Erow[4*q + 1], a5);
                a6 = fmaf(v.z, Erow[4*q + 2], a6);
                a7 = fmaf(v.w, Erow[4*q + 3], a7);
            } else {
                a0 = fmaf(v.x, Erow[4*q    ], a0);
                a1 = fmaf(v.y, Erow[4*q + 1], a1);
                a2 = fmaf(v.z, Erow[4*q + 2], a2);
                a3 = fmaf(v.w, Erow[4*q + 3], a3);
            }
            if (renorm) {
                float mv = fmaxf(fmaxf(v.x, v.y), fmaxf(v.z, v.w));
                if (q & 1) mB = fmaxf(mB, mv); else mA = fmaxf(mA, mv);
            }
        }
        float acc = ((a0+a1) + (a2+a3)) + ((a4+a5) + (a6+a7));
        float dn = acc * se;

        if (renorm) {
            float m = fmaxf(fmaxf(mA, mB), 1e-30f);   // exact block max of d_{t-1}
            dn *= rcpf(m);
            C += lg2f(m);
        }
        ds[cur ^ 1][j] = dn;          // write other buffer: no WAR with this step's reads
        BAR64();                      // one barrier per step
        cur ^= 1;
    };

    // head peel t=1..7
#pragma unroll
    for (int t = 1; t <= 7; ++t) STEP(t, t - 1, false, true);

    // main chunks of 8 (renorm at i==0 -> t % 8 == 0)
    int tb = 8;
    for (; tb + 8 <= len; tb += 8) {
#pragma unroll
        for (int i = 0; i < 8; ++i)
            STEP(tb + i, (i + 7) & 7, i == 0, true);
    }
    // tail: direct loads, runtime renorm flag
    for (int t = tb; t < len; ++t)
        STEP(t, 0, (t & 7) == 0, false);

    // ---- final logsumexp over the 64 states ----
    float v = ds[cur][j];
#pragma unroll
    for (int o = 16; o > 0; o >>= 1) v += __shfl_xor_sync(0xffffffffu, v, o);
    if (lane == 0) s_red[warp] = v;   // warp = 0 or 1
    BAR64();
    if (tid == 0) {
        const float S = s_red[0] + s_red[1];
        const float logz2 = C + ESHIFT * (float)(len - 1) + lg2f(S);
        out[b] = (logz2 - s_score) * LN2;
    }
}

// ---------------------------------------------------------------
extern "C" void kernel_launch(void* const* d_in, const int* in_sizes, int n_in,
                              void* d_out, int out_size)
{
    const float*         features = (const float*)d_in[0];
    const float*         W        = (const float*)d_in[1];
    const float*         bias     = (const float*)d_in[2];
    const float*         trans    = (const float*)d_in[3];
    const int*           tagsraw  = (const int*)d_in[4];
    const unsigned char* maskraw  = (const unsigned char*)d_in[5];
    float*               out      = (float*)d_out;

    detect_kernel<<<1, 256>>>((const unsigned int*)tagsraw, maskraw);
    convert_kernel<<<B_, 256>>>(tagsraw, maskraw);
    prep_kernel<<<192, 256>>>(W, trans);
    fused_kernel<<<M_ / BM, 256>>>(features, bias, out);
}